// round 2
// baseline (speedup 1.0000x reference)
#include <cuda_runtime.h>

#define NNODES 50000
#define NEDGES 800000
#define ETOT   850000
#define FIN    128
#define H1     4
#define C1     64
#define D1     256   // H1*C1
#define D2     64
#define NEG_SLOPE 0.2f

// ---------------- scratch (static device globals; no runtime allocation) ----
static __device__ float g_xl1 [NNODES * D1];   // x @ W1            (51.2 MB)
static __device__ float g_agg1[NNODES * D1];   // layer1 agg -> ELU (51.2 MB)
static __device__ float g_xl2 [NNODES * D2];   // h @ W2            (12.8 MB)
static __device__ float g_as1 [NNODES * H1];
static __device__ float g_ad1 [NNODES * H1];
static __device__ float g_m1  [NNODES * H1];
static __device__ float g_s1  [NNODES * H1];
static __device__ float g_ex1 [ETOT * H1];     // per-edge exp      (13.6 MB)
static __device__ float g_as2 [NNODES];
static __device__ float g_ad2 [NNODES];
static __device__ float g_m2  [NNODES];
static __device__ float g_s2  [NNODES];
static __device__ float g_ex2 [ETOT];

// ---------------- helpers ---------------------------------------------------
__device__ __forceinline__ void atomicMaxFloat(float* addr, float val) {
    // valid for non-NaN floats
    if (val >= 0.f) atomicMax((int*)addr, __float_as_int(val));
    else            atomicMin((unsigned int*)addr, (unsigned int)__float_as_int(val));
}

// edge_index is int32 on-device (harness converts int64 -> int32)
__device__ __forceinline__ void edge_nodes(const int* __restrict__ ei,
                                           int e, int& s, int& d) {
    if (e < NEDGES) { s = ei[e]; d = ei[NEDGES + e]; }
    else            { s = e - NEDGES; d = s; }
}

// ---------------- init (zeros + -inf), grid-stride over 12.8M ---------------
__global__ void init_kernel(float* __restrict__ agg1, float* __restrict__ out,
                            float* __restrict__ s1, float* __restrict__ s2,
                            float* __restrict__ m1, float* __restrict__ m2) {
    const float NEG_INF = __int_as_float(0xFF800000);
    for (int i = blockIdx.x * blockDim.x + threadIdx.x;
         i < NNODES * D1; i += gridDim.x * blockDim.x) {
        agg1[i] = 0.f;
        if (i < NNODES * D2) out[i] = 0.f;
        if (i < NNODES * H1) { s1[i] = 0.f; m1[i] = NEG_INF; }
        if (i < NNODES)      { s2[i] = 0.f; m2[i] = NEG_INF; }
    }
}

// ---------------- SGEMM (A[MxK] row-major @ B[KxN] row-major -> C[MxN]) -----
#define BM 64
#define BN 64
#define BK 16
__global__ void sgemm(const float* __restrict__ A, const float* __restrict__ B,
                      float* __restrict__ C, int M, int K, int N) {
    __shared__ float As[BK][BM + 1];
    __shared__ float Bs[BK][BN];
    int t  = threadIdx.x;
    int ty = t >> 4, tx = t & 15;
    int row0 = blockIdx.y * BM;
    int col0 = blockIdx.x * BN;
    float acc[4][4] = {};
    for (int k0 = 0; k0 < K; k0 += BK) {
        #pragma unroll
        for (int i = 0; i < 4; i++) {
            int idx = t + i * 256;
            int r = idx / BK, c = idx % BK;
            int gr = row0 + r;
            As[c][r] = (gr < M) ? A[(long)gr * K + k0 + c] : 0.f;
        }
        #pragma unroll
        for (int i = 0; i < 4; i++) {
            int idx = t + i * 256;
            int r = idx / BN, c = idx % BN;
            Bs[r][c] = B[(long)(k0 + r) * N + col0 + c];
        }
        __syncthreads();
        #pragma unroll
        for (int k = 0; k < BK; k++) {
            float a[4], b[4];
            #pragma unroll
            for (int i = 0; i < 4; i++) a[i] = As[k][ty * 4 + i];
            #pragma unroll
            for (int j = 0; j < 4; j++) b[j] = Bs[k][tx * 4 + j];
            #pragma unroll
            for (int i = 0; i < 4; i++)
                #pragma unroll
                for (int j = 0; j < 4; j++)
                    acc[i][j] += a[i] * b[j];
        }
        __syncthreads();
    }
    #pragma unroll
    for (int i = 0; i < 4; i++) {
        int gr = row0 + ty * 4 + i;
        if (gr < M) {
            #pragma unroll
            for (int j = 0; j < 4; j++)
                C[(long)gr * N + col0 + tx * 4 + j] = acc[i][j];
        }
    }
}

// ---------------- per-node attention coefficients ---------------------------
__global__ void alpha1_kernel(const float* __restrict__ xl,
                              const float* __restrict__ att_s,
                              const float* __restrict__ att_d,
                              float* __restrict__ asrc, float* __restrict__ adst) {
    int w = (blockIdx.x * blockDim.x + threadIdx.x) >> 5;
    int lane = threadIdx.x & 31;
    if (w >= NNODES) return;
    const float* row = xl + (long)w * D1;
    float ps[H1] = {}, pd[H1] = {};
    #pragma unroll
    for (int j = 0; j < 8; j++) {
        int c = lane + j * 32;
        float v = row[c];
        int h = j >> 1;
        ps[h] += v * att_s[c];
        pd[h] += v * att_d[c];
    }
    #pragma unroll
    for (int off = 16; off; off >>= 1) {
        #pragma unroll
        for (int h = 0; h < H1; h++) {
            ps[h] += __shfl_xor_sync(0xFFFFFFFFu, ps[h], off);
            pd[h] += __shfl_xor_sync(0xFFFFFFFFu, pd[h], off);
        }
    }
    if (lane == 0) {
        #pragma unroll
        for (int h = 0; h < H1; h++) {
            asrc[w * H1 + h] = ps[h];
            adst[w * H1 + h] = pd[h];
        }
    }
}

__global__ void alpha2_kernel(const float* __restrict__ xl,
                              const float* __restrict__ att_s,
                              const float* __restrict__ att_d,
                              float* __restrict__ asrc, float* __restrict__ adst) {
    int w = (blockIdx.x * blockDim.x + threadIdx.x) >> 5;
    int lane = threadIdx.x & 31;
    if (w >= NNODES) return;
    const float* row = xl + (long)w * D2;
    float v0 = row[lane], v1 = row[lane + 32];
    float ps = v0 * att_s[lane] + v1 * att_s[lane + 32];
    float pd = v0 * att_d[lane] + v1 * att_d[lane + 32];
    #pragma unroll
    for (int off = 16; off; off >>= 1) {
        ps += __shfl_xor_sync(0xFFFFFFFFu, ps, off);
        pd += __shfl_xor_sync(0xFFFFFFFFu, pd, off);
    }
    if (lane == 0) { asrc[w] = ps; adst[w] = pd; }
}

// ---------------- edge softmax passes ---------------------------------------
__global__ void edge_max1(const int* __restrict__ ei,
                          const float* __restrict__ asrc, const float* __restrict__ adst,
                          float* __restrict__ m) {
    int e = blockIdx.x * blockDim.x + threadIdx.x;
    if (e >= ETOT) return;
    int s, d; edge_nodes(ei, e, s, d);
    #pragma unroll
    for (int h = 0; h < H1; h++) {
        float v = asrc[s * H1 + h] + adst[d * H1 + h];
        v = v > 0.f ? v : v * NEG_SLOPE;
        atomicMaxFloat(&m[d * H1 + h], v);
    }
}

__global__ void edge_exp1(const int* __restrict__ ei,
                          const float* __restrict__ asrc, const float* __restrict__ adst,
                          const float* __restrict__ m, float* __restrict__ ssum,
                          float* __restrict__ exbuf) {
    int e = blockIdx.x * blockDim.x + threadIdx.x;
    if (e >= ETOT) return;
    int s, d; edge_nodes(ei, e, s, d);
    #pragma unroll
    for (int h = 0; h < H1; h++) {
        float v = asrc[s * H1 + h] + adst[d * H1 + h];
        v = v > 0.f ? v : v * NEG_SLOPE;
        float ex = __expf(v - m[d * H1 + h]);
        exbuf[(long)e * H1 + h] = ex;
        atomicAdd(&ssum[d * H1 + h], ex);
    }
}

__global__ void edge_max2(const int* __restrict__ ei,
                          const float* __restrict__ asrc, const float* __restrict__ adst,
                          float* __restrict__ m) {
    int e = blockIdx.x * blockDim.x + threadIdx.x;
    if (e >= ETOT) return;
    int s, d; edge_nodes(ei, e, s, d);
    float v = asrc[s] + adst[d];
    v = v > 0.f ? v : v * NEG_SLOPE;
    atomicMaxFloat(&m[d], v);
}

__global__ void edge_exp2(const int* __restrict__ ei,
                          const float* __restrict__ asrc, const float* __restrict__ adst,
                          const float* __restrict__ m, float* __restrict__ ssum,
                          float* __restrict__ exbuf) {
    int e = blockIdx.x * blockDim.x + threadIdx.x;
    if (e >= ETOT) return;
    int s, d; edge_nodes(ei, e, s, d);
    float v = asrc[s] + adst[d];
    v = v > 0.f ? v : v * NEG_SLOPE;
    float ex = __expf(v - m[d]);
    exbuf[e] = ex;
    atomicAdd(&ssum[d], ex);
}

// ---------------- aggregation ------------------------------------------------
__global__ void agg1_kernel(const int* __restrict__ ei,
                            const float* __restrict__ exbuf, const float* __restrict__ ssum,
                            const float* __restrict__ xl, float* __restrict__ out) {
    int e = blockIdx.x;
    int t = threadIdx.x;
    int s, d; edge_nodes(ei, e, s, d);
    int h = t >> 6;
    float alpha = exbuf[(long)e * H1 + h] / ssum[d * H1 + h];
    atomicAdd(&out[(long)d * D1 + t], alpha * xl[(long)s * D1 + t]);
}

__global__ void agg2_kernel(const int* __restrict__ ei,
                            const float* __restrict__ exbuf, const float* __restrict__ ssum,
                            const float* __restrict__ xl, float* __restrict__ out) {
    int e = blockIdx.x * 4 + (threadIdx.x >> 6);
    int c = threadIdx.x & 63;
    if (e >= ETOT) return;
    int s, d; edge_nodes(ei, e, s, d);
    float alpha = exbuf[e] / ssum[d];
    atomicAdd(&out[(long)d * D2 + c], alpha * xl[(long)s * D2 + c]);
}

// ---------------- epilogues --------------------------------------------------
__global__ void elu_bias_kernel(float* __restrict__ a, const float* __restrict__ b) {
    int i = blockIdx.x * blockDim.x + threadIdx.x;   // exactly N*D1 threads
    float v = a[i] + b[i & (D1 - 1)];
    a[i] = v > 0.f ? v : (__expf(v) - 1.f);
}

__global__ void bias2_kernel(float* __restrict__ out, const float* __restrict__ b) {
    int i = blockIdx.x * blockDim.x + threadIdx.x;
    if (i < NNODES * D2) out[i] += b[i & (D2 - 1)];
}

// ---------------- launch -----------------------------------------------------
extern "C" void kernel_launch(void* const* d_in, const int* in_sizes, int n_in,
                              void* d_out, int out_size) {
    const float* x     = (const float*)d_in[0];
    const int*   ei    = (const int*)d_in[1];     // int64 in reference -> int32 on device
    const float* W1    = (const float*)d_in[2];
    const float* at_s1 = (const float*)d_in[3];
    const float* at_d1 = (const float*)d_in[4];
    const float* b1    = (const float*)d_in[5];
    const float* W2    = (const float*)d_in[6];
    const float* at_s2 = (const float*)d_in[7];
    const float* at_d2 = (const float*)d_in[8];
    const float* b2    = (const float*)d_in[9];
    float* out = (float*)d_out;

    float *xl1, *agg1, *xl2, *as1, *ad1, *m1, *s1, *ex1, *as2, *ad2, *m2, *s2, *ex2;
    cudaGetSymbolAddress((void**)&xl1,  g_xl1);
    cudaGetSymbolAddress((void**)&agg1, g_agg1);
    cudaGetSymbolAddress((void**)&xl2,  g_xl2);
    cudaGetSymbolAddress((void**)&as1,  g_as1);
    cudaGetSymbolAddress((void**)&ad1,  g_ad1);
    cudaGetSymbolAddress((void**)&m1,   g_m1);
    cudaGetSymbolAddress((void**)&s1,   g_s1);
    cudaGetSymbolAddress((void**)&ex1,  g_ex1);
    cudaGetSymbolAddress((void**)&as2,  g_as2);
    cudaGetSymbolAddress((void**)&ad2,  g_ad2);
    cudaGetSymbolAddress((void**)&m2,   g_m2);
    cudaGetSymbolAddress((void**)&s2,   g_s2);
    cudaGetSymbolAddress((void**)&ex2,  g_ex2);

    init_kernel<<<2048, 256>>>(agg1, out, s1, s2, m1, m2);

    // ---- layer 1 ----
    sgemm<<<dim3(D1 / BN, (NNODES + BM - 1) / BM), 256>>>(x, W1, xl1, NNODES, FIN, D1);
    alpha1_kernel<<<(NNODES * 32 + 255) / 256, 256>>>(xl1, at_s1, at_d1, as1, ad1);
    edge_max1<<<(ETOT + 255) / 256, 256>>>(ei, as1, ad1, m1);
    edge_exp1<<<(ETOT + 255) / 256, 256>>>(ei, as1, ad1, m1, s1, ex1);
    agg1_kernel<<<ETOT, 256>>>(ei, ex1, s1, xl1, agg1);
    elu_bias_kernel<<<NNODES * D1 / 256, 256>>>(agg1, b1);

    // ---- layer 2 ----
    sgemm<<<dim3(D2 / BN, (NNODES + BM - 1) / BM), 256>>>(agg1, W2, xl2, NNODES, D1, D2);
    alpha2_kernel<<<(NNODES * 32 + 255) / 256, 256>>>(xl2, at_s2, at_d2, as2, ad2);
    edge_max2<<<(ETOT + 255) / 256, 256>>>(ei, as2, ad2, m2);
    edge_exp2<<<(ETOT + 255) / 256, 256>>>(ei, as2, ad2, m2, s2, ex2);
    agg2_kernel<<<(ETOT + 3) / 4, 256>>>(ei, ex2, s2, xl2, out);
    bias2_kernel<<<(NNODES * D2 + 255) / 256, 256>>>(out, b2);
}

// round 3
// speedup vs baseline: 1.6200x; 1.6200x over previous
#include <cuda_runtime.h>

#define NNODES 50000
#define NEDGES 800000
#define ETOT   850000
#define FIN    128
#define H1     4
#define D1     256   // H1*C1
#define D2     64
#define NEG_SLOPE 0.2f

// ---------------- scratch (static device globals) ---------------------------
static __device__ float g_xl1 [NNODES * D1];   // x @ W1            (51.2 MB)
static __device__ float g_agg1[NNODES * D1];   // layer1 agg        (51.2 MB)
static __device__ float g_xl2 [NNODES * D2];   // h @ W2            (12.8 MB)
static __device__ float g_as1 [NNODES * H1];
static __device__ float g_ad1 [NNODES * H1];
static __device__ float g_s1  [NNODES * H1];
static __device__ float g_ex1 [ETOT * H1];     // per-edge exp      (13.6 MB)
static __device__ float g_as2 [NNODES];
static __device__ float g_ad2 [NNODES];
static __device__ float g_s2  [NNODES];
static __device__ float g_ex2 [ETOT];

__device__ __forceinline__ void edge_nodes(const int* __restrict__ ei,
                                           int e, int& s, int& d) {
    if (e < NEDGES) { s = ei[e]; d = ei[NEDGES + e]; }
    else            { s = e - NEDGES; d = s; }
}

// ---------------- init ------------------------------------------------------
__global__ void init_kernel(float* __restrict__ agg1, float* __restrict__ out,
                            float* __restrict__ s1, float* __restrict__ s2,
                            const float* __restrict__ b2) {
    for (int i = blockIdx.x * blockDim.x + threadIdx.x;
         i < NNODES * D1; i += gridDim.x * blockDim.x) {
        agg1[i] = 0.f;
        if (i < NNODES * D2) out[i] = b2[i & (D2 - 1)];
        if (i < NNODES * H1) s1[i] = 0.f;
        if (i < NNODES)      s2[i] = 0.f;
    }
}

// ---------------- SGEMM1: [M x 128] @ [128 x 256], BM=128 BN=128 BK=16 ------
// 256 threads, 8x8 per thread, float4 vectorized.
__global__ __launch_bounds__(256) void sgemm1_kernel(
    const float* __restrict__ A, const float* __restrict__ B,
    float* __restrict__ C, int M) {
    const int K = FIN, N = D1;
    __shared__ float As[16][128];
    __shared__ float Bs[16][128];
    int tid = threadIdx.x;
    int tx = tid & 15, ty = tid >> 4;          // 16 x 16 threads
    int row0 = blockIdx.y * 128;
    int col0 = blockIdx.x * 128;
    float acc[8][8] = {};
    float4 a0, a1, b0, b1;

    for (int k0 = 0; k0 < K; k0 += 16) {
        // A tile: 128 rows x 16 cols = 512 float4, 2 per thread (transpose)
        #pragma unroll
        for (int i = 0; i < 2; i++) {
            int idx = tid + i * 256;
            int r = idx >> 2, kc = (idx & 3) * 4;
            int gr = row0 + r;
            float4 v = make_float4(0.f, 0.f, 0.f, 0.f);
            if (gr < M) v = *(const float4*)(A + (long)gr * K + k0 + kc);
            As[kc + 0][r] = v.x; As[kc + 1][r] = v.y;
            As[kc + 2][r] = v.z; As[kc + 3][r] = v.w;
        }
        // B tile: 16 rows x 128 cols = 512 float4, 2 per thread
        #pragma unroll
        for (int i = 0; i < 2; i++) {
            int idx = tid + i * 256;
            int r = idx >> 5, c = (idx & 31) * 4;
            *(float4*)(&Bs[r][c]) = *(const float4*)(B + (long)(k0 + r) * N + col0 + c);
        }
        __syncthreads();
        #pragma unroll
        for (int k = 0; k < 16; k++) {
            a0 = *(const float4*)(&As[k][ty * 8]);
            a1 = *(const float4*)(&As[k][ty * 8 + 4]);
            b0 = *(const float4*)(&Bs[k][tx * 8]);
            b1 = *(const float4*)(&Bs[k][tx * 8 + 4]);
            float av[8] = {a0.x, a0.y, a0.z, a0.w, a1.x, a1.y, a1.z, a1.w};
            float bv[8] = {b0.x, b0.y, b0.z, b0.w, b1.x, b1.y, b1.z, b1.w};
            #pragma unroll
            for (int i = 0; i < 8; i++)
                #pragma unroll
                for (int j = 0; j < 8; j++)
                    acc[i][j] += av[i] * bv[j];
        }
        __syncthreads();
    }
    #pragma unroll
    for (int i = 0; i < 8; i++) {
        int gr = row0 + ty * 8 + i;
        if (gr < M) {
            *(float4*)(C + (long)gr * N + col0 + tx * 8)     =
                make_float4(acc[i][0], acc[i][1], acc[i][2], acc[i][3]);
            *(float4*)(C + (long)gr * N + col0 + tx * 8 + 4) =
                make_float4(acc[i][4], acc[i][5], acc[i][6], acc[i][7]);
        }
    }
}

// ---------------- SGEMM2: [M x 256] @ [256 x 64] with fused ELU+bias on A ---
// BM=128 BN=64 BK=16, 256 threads, 8x4 per thread.
__global__ __launch_bounds__(256) void sgemm2_kernel(
    const float* __restrict__ A, const float* __restrict__ bias1,
    const float* __restrict__ B, float* __restrict__ C, int M) {
    const int K = D1, N = D2;
    __shared__ float As[16][128];
    __shared__ float Bs[16][64];
    int tid = threadIdx.x;
    int tx = tid & 15, ty = tid >> 4;          // col = tx*4, row = ty*8
    int row0 = blockIdx.y * 128;
    float acc[8][4] = {};

    for (int k0 = 0; k0 < K; k0 += 16) {
        #pragma unroll
        for (int i = 0; i < 2; i++) {
            int idx = tid + i * 256;
            int r = idx >> 2, kc = (idx & 3) * 4;
            int gr = row0 + r;
            float4 v = make_float4(0.f, 0.f, 0.f, 0.f);
            if (gr < M) {
                v = *(const float4*)(A + (long)gr * K + k0 + kc);
                float4 bb = *(const float4*)(bias1 + k0 + kc);
                v.x += bb.x; v.y += bb.y; v.z += bb.z; v.w += bb.w;
                v.x = v.x > 0.f ? v.x : (__expf(v.x) - 1.f);
                v.y = v.y > 0.f ? v.y : (__expf(v.y) - 1.f);
                v.z = v.z > 0.f ? v.z : (__expf(v.z) - 1.f);
                v.w = v.w > 0.f ? v.w : (__expf(v.w) - 1.f);
            }
            As[kc + 0][r] = v.x; As[kc + 1][r] = v.y;
            As[kc + 2][r] = v.z; As[kc + 3][r] = v.w;
        }
        {
            int r = tid >> 4, c = (tid & 15) * 4;   // 16 x 64 = 256 float4
            *(float4*)(&Bs[r][c]) = *(const float4*)(B + (long)(k0 + r) * N + c);
        }
        __syncthreads();
        #pragma unroll
        for (int k = 0; k < 16; k++) {
            float4 a0 = *(const float4*)(&As[k][ty * 8]);
            float4 a1 = *(const float4*)(&As[k][ty * 8 + 4]);
            float4 b0 = *(const float4*)(&Bs[k][tx * 4]);
            float av[8] = {a0.x, a0.y, a0.z, a0.w, a1.x, a1.y, a1.z, a1.w};
            float bv[4] = {b0.x, b0.y, b0.z, b0.w};
            #pragma unroll
            for (int i = 0; i < 8; i++)
                #pragma unroll
                for (int j = 0; j < 4; j++)
                    acc[i][j] += av[i] * bv[j];
        }
        __syncthreads();
    }
    #pragma unroll
    for (int i = 0; i < 8; i++) {
        int gr = row0 + ty * 8 + i;
        if (gr < M)
            *(float4*)(C + (long)gr * N + tx * 4) =
                make_float4(acc[i][0], acc[i][1], acc[i][2], acc[i][3]);
    }
}

// ---------------- per-node attention coefficients ---------------------------
__global__ void alpha1_kernel(const float* __restrict__ xl,
                              const float* __restrict__ att_s,
                              const float* __restrict__ att_d,
                              float* __restrict__ asrc, float* __restrict__ adst) {
    int w = (blockIdx.x * blockDim.x + threadIdx.x) >> 5;
    int lane = threadIdx.x & 31;
    if (w >= NNODES) return;
    const float* row = xl + (long)w * D1;
    float ps[H1] = {}, pd[H1] = {};
    #pragma unroll
    for (int j = 0; j < 8; j++) {
        int c = lane + j * 32;
        float v = row[c];
        int h = j >> 1;
        ps[h] += v * att_s[c];
        pd[h] += v * att_d[c];
    }
    #pragma unroll
    for (int off = 16; off; off >>= 1) {
        #pragma unroll
        for (int h = 0; h < H1; h++) {
            ps[h] += __shfl_xor_sync(0xFFFFFFFFu, ps[h], off);
            pd[h] += __shfl_xor_sync(0xFFFFFFFFu, pd[h], off);
        }
    }
    if (lane == 0) {
        *(float4*)(asrc + w * H1) = make_float4(ps[0], ps[1], ps[2], ps[3]);
        *(float4*)(adst + w * H1) = make_float4(pd[0], pd[1], pd[2], pd[3]);
    }
}

__global__ void alpha2_kernel(const float* __restrict__ xl,
                              const float* __restrict__ att_s,
                              const float* __restrict__ att_d,
                              float* __restrict__ asrc, float* __restrict__ adst) {
    int w = (blockIdx.x * blockDim.x + threadIdx.x) >> 5;
    int lane = threadIdx.x & 31;
    if (w >= NNODES) return;
    const float* row = xl + (long)w * D2;
    float v0 = row[lane], v1 = row[lane + 32];
    float ps = v0 * att_s[lane] + v1 * att_s[lane + 32];
    float pd = v0 * att_d[lane] + v1 * att_d[lane + 32];
    #pragma unroll
    for (int off = 16; off; off >>= 1) {
        ps += __shfl_xor_sync(0xFFFFFFFFu, ps, off);
        pd += __shfl_xor_sync(0xFFFFFFFFu, pd, off);
    }
    if (lane == 0) { asrc[w] = ps; adst[w] = pd; }
}

// ---------------- edge exp + sum (no max subtraction needed) -----------------
__global__ void edge_exp1(const int* __restrict__ ei,
                          const float* __restrict__ asrc, const float* __restrict__ adst,
                          float* __restrict__ ssum, float* __restrict__ exbuf) {
    int e = blockIdx.x * blockDim.x + threadIdx.x;
    if (e >= ETOT) return;
    int s, d; edge_nodes(ei, e, s, d);
    float4 as = *(const float4*)(asrc + s * H1);
    float4 ad = *(const float4*)(adst + d * H1);
    float v[4] = {as.x + ad.x, as.y + ad.y, as.z + ad.z, as.w + ad.w};
    float ex[4];
    #pragma unroll
    for (int h = 0; h < H1; h++) {
        float t = v[h] > 0.f ? v[h] : v[h] * NEG_SLOPE;
        ex[h] = __expf(t);
        atomicAdd(&ssum[d * H1 + h], ex[h]);
    }
    *(float4*)(exbuf + (long)e * H1) = make_float4(ex[0], ex[1], ex[2], ex[3]);
}

__global__ void edge_exp2(const int* __restrict__ ei,
                          const float* __restrict__ asrc, const float* __restrict__ adst,
                          float* __restrict__ ssum, float* __restrict__ exbuf) {
    int e = blockIdx.x * blockDim.x + threadIdx.x;
    if (e >= ETOT) return;
    int s, d; edge_nodes(ei, e, s, d);
    float v = asrc[s] + adst[d];
    v = v > 0.f ? v : v * NEG_SLOPE;
    float ex = __expf(v);
    exbuf[e] = ex;
    atomicAdd(&ssum[d], ex);
}

// ---------------- aggregation (float4 gathers, scalar atomics) ---------------
// layer1: 4 edges per 256-thread block; 64 threads x float4 = 256 ch per edge
__global__ void agg1_kernel(const int* __restrict__ ei,
                            const float* __restrict__ exbuf, const float* __restrict__ ssum,
                            const float* __restrict__ xl, float* __restrict__ out) {
    int e = blockIdx.x * 4 + (threadIdx.x >> 6);
    if (e >= ETOT) return;
    int c4 = threadIdx.x & 63;                 // float4 index, 0..63
    int s, d; edge_nodes(ei, e, s, d);
    int h = c4 >> 4;
    float alpha = exbuf[(long)e * H1 + h] / ssum[d * H1 + h];
    float4 v = *(const float4*)(xl + (long)s * D1 + c4 * 4);
    float* o = out + (long)d * D1 + c4 * 4;
    atomicAdd(o + 0, alpha * v.x);
    atomicAdd(o + 1, alpha * v.y);
    atomicAdd(o + 2, alpha * v.z);
    atomicAdd(o + 3, alpha * v.w);
}

// layer2: 16 edges per 256-thread block; 16 threads x float4 = 64 ch per edge
__global__ void agg2_kernel(const int* __restrict__ ei,
                            const float* __restrict__ exbuf, const float* __restrict__ ssum,
                            const float* __restrict__ xl, float* __restrict__ out) {
    int e = blockIdx.x * 16 + (threadIdx.x >> 4);
    if (e >= ETOT) return;
    int c4 = threadIdx.x & 15;
    int s, d; edge_nodes(ei, e, s, d);
    float alpha = exbuf[e] / ssum[d];
    float4 v = *(const float4*)(xl + (long)s * D2 + c4 * 4);
    float* o = out + (long)d * D2 + c4 * 4;
    atomicAdd(o + 0, alpha * v.x);
    atomicAdd(o + 1, alpha * v.y);
    atomicAdd(o + 2, alpha * v.z);
    atomicAdd(o + 3, alpha * v.w);
}

// ---------------- launch -----------------------------------------------------
extern "C" void kernel_launch(void* const* d_in, const int* in_sizes, int n_in,
                              void* d_out, int out_size) {
    const float* x     = (const float*)d_in[0];
    const int*   ei    = (const int*)d_in[1];
    const float* W1    = (const float*)d_in[2];
    const float* at_s1 = (const float*)d_in[3];
    const float* at_d1 = (const float*)d_in[4];
    const float* b1    = (const float*)d_in[5];
    const float* W2    = (const float*)d_in[6];
    const float* at_s2 = (const float*)d_in[7];
    const float* at_d2 = (const float*)d_in[8];
    const float* b2    = (const float*)d_in[9];
    float* out = (float*)d_out;

    float *xl1, *agg1, *xl2, *as1, *ad1, *s1, *ex1, *as2, *ad2, *s2, *ex2;
    cudaGetSymbolAddress((void**)&xl1,  g_xl1);
    cudaGetSymbolAddress((void**)&agg1, g_agg1);
    cudaGetSymbolAddress((void**)&xl2,  g_xl2);
    cudaGetSymbolAddress((void**)&as1,  g_as1);
    cudaGetSymbolAddress((void**)&ad1,  g_ad1);
    cudaGetSymbolAddress((void**)&s1,   g_s1);
    cudaGetSymbolAddress((void**)&ex1,  g_ex1);
    cudaGetSymbolAddress((void**)&as2,  g_as2);
    cudaGetSymbolAddress((void**)&ad2,  g_ad2);
    cudaGetSymbolAddress((void**)&s2,   g_s2);
    cudaGetSymbolAddress((void**)&ex2,  g_ex2);

    init_kernel<<<2048, 256>>>(agg1, out, s1, s2, b2);

    // ---- layer 1 ----
    sgemm1_kernel<<<dim3(D1 / 128, (NNODES + 127) / 128), 256>>>(x, W1, xl1, NNODES);
    alpha1_kernel<<<(NNODES * 32 + 255) / 256, 256>>>(xl1, at_s1, at_d1, as1, ad1);
    edge_exp1<<<(ETOT + 255) / 256, 256>>>(ei, as1, ad1, s1, ex1);
    agg1_kernel<<<(ETOT + 3) / 4, 256>>>(ei, ex1, s1, xl1, agg1);

    // ---- layer 2 (ELU + b1 fused into sgemm2 A-load; b2 fused into init) ----
    sgemm2_kernel<<<dim3(1, (NNODES + 127) / 128), 256>>>(agg1, b1, W2, xl2, NNODES);
    alpha2_kernel<<<(NNODES * 32 + 255) / 256, 256>>>(xl2, at_s2, at_d2, as2, ad2);
    edge_exp2<<<(ETOT + 255) / 256, 256>>>(ei, as2, ad2, s2, ex2);
    agg2_kernel<<<(ETOT + 15) / 16, 256>>>(ei, ex2, s2, xl2, out);
}

// round 6
// speedup vs baseline: 4.5321x; 2.7977x over previous
#include <cuda_runtime.h>

#define NNODES 50000
#define NEDGES 800000
#define ETOT   850000
#define FIN    128
#define H1     4
#define D1     256   // H1*C1
#define D2     64
#define NEG_SLOPE 0.2f
#define NBLK_SCAN 196   // ceil(50000/256)

// ---------------- scratch (static device globals) ---------------------------
static __device__ float g_xl1 [NNODES * D1];   // x @ W1                (51.2 MB)
static __device__ float g_agg1[NNODES * D1];   // layer1 normalized agg (51.2 MB)
static __device__ float g_xl2 [NNODES * D2];   // h @ W2                (12.8 MB)
static __device__ float g_as1 [NNODES * H1];
static __device__ float g_ad1 [NNODES * H1];
static __device__ float g_as2 [NNODES];
static __device__ float g_ad2 [NNODES];
static __device__ int   g_cnt [NNODES];
static __device__ int   g_rowptr[NNODES + 1];
static __device__ int   g_wptr[NNODES];
static __device__ int   g_bsum[256];
static __device__ int   g_boff[256];
static __device__ int   g_srcs[ETOT];

__device__ __forceinline__ void edge_nodes(const int* __restrict__ ei,
                                           int e, int& s, int& d) {
    if (e < NEDGES) { s = ei[e]; d = ei[NEDGES + e]; }
    else            { s = e - NEDGES; d = s; }
}

// ================= CSR build =================================================
__global__ void zero_cnt(int* __restrict__ cnt) {
    int i = blockIdx.x * blockDim.x + threadIdx.x;
    if (i < NNODES) cnt[i] = 0;
}

__global__ void hist_kernel(const int* __restrict__ ei, int* __restrict__ cnt) {
    int e = blockIdx.x * blockDim.x + threadIdx.x;
    if (e >= ETOT) return;
    int s, d; edge_nodes(ei, e, s, d);
    atomicAdd(&cnt[d], 1);
}

__global__ void scan1_kernel(const int* __restrict__ cnt,
                             int* __restrict__ rowptr, int* __restrict__ bsum) {
    __shared__ int sm[256];
    int tid = threadIdx.x;
    int i = blockIdx.x * 256 + tid;
    int val = (i < NNODES) ? cnt[i] : 0;
    sm[tid] = val;
    __syncthreads();
    #pragma unroll
    for (int off = 1; off < 256; off <<= 1) {
        int t = (tid >= off) ? sm[tid - off] : 0;
        __syncthreads();
        sm[tid] += t;
        __syncthreads();
    }
    if (i < NNODES) rowptr[i] = sm[tid] - val;          // exclusive within block
    if (tid == 255) bsum[blockIdx.x] = sm[tid];         // block total
}

__global__ void scan2_kernel(int* __restrict__ bsum, int* __restrict__ boff) {
    __shared__ int sm[256];
    int tid = threadIdx.x;
    int val = (tid < NBLK_SCAN) ? bsum[tid] : 0;
    sm[tid] = val;
    __syncthreads();
    #pragma unroll
    for (int off = 1; off < 256; off <<= 1) {
        int t = (tid >= off) ? sm[tid - off] : 0;
        __syncthreads();
        sm[tid] += t;
        __syncthreads();
    }
    boff[tid] = sm[tid] - val;                          // exclusive
}

__global__ void scan3_kernel(int* __restrict__ rowptr, const int* __restrict__ boff,
                             int* __restrict__ wptr) {
    int i = blockIdx.x * blockDim.x + threadIdx.x;
    if (i < NNODES) {
        int r = rowptr[i] + boff[i >> 8];
        rowptr[i] = r;
        wptr[i]   = r;
    }
    if (i == 0) rowptr[NNODES] = ETOT;
}

__global__ void scatter_kernel(const int* __restrict__ ei, int* __restrict__ wptr,
                               int* __restrict__ srcs) {
    int e = blockIdx.x * blockDim.x + threadIdx.x;
    if (e >= ETOT) return;
    int s, d; edge_nodes(ei, e, s, d);
    srcs[atomicAdd(&wptr[d], 1)] = s;
}

// ================= SGEMM1: [M x 128] @ [128 x 256] ===========================
__global__ __launch_bounds__(256) void sgemm1_kernel(
    const float* __restrict__ A, const float* __restrict__ B,
    float* __restrict__ C, int M) {
    const int K = FIN, N = D1;
    __shared__ float As[16][128];
    __shared__ float Bs[16][128];
    int tid = threadIdx.x;
    int tx = tid & 15, ty = tid >> 4;
    int row0 = blockIdx.y * 128;
    int col0 = blockIdx.x * 128;
    float acc[8][8] = {};
    for (int k0 = 0; k0 < K; k0 += 16) {
        #pragma unroll
        for (int i = 0; i < 2; i++) {
            int idx = tid + i * 256;
            int r = idx >> 2, kc = (idx & 3) * 4;
            int gr = row0 + r;
            float4 v = make_float4(0.f, 0.f, 0.f, 0.f);
            if (gr < M) v = *(const float4*)(A + (long)gr * K + k0 + kc);
            As[kc + 0][r] = v.x; As[kc + 1][r] = v.y;
            As[kc + 2][r] = v.z; As[kc + 3][r] = v.w;
        }
        #pragma unroll
        for (int i = 0; i < 2; i++) {
            int idx = tid + i * 256;
            int r = idx >> 5, c = (idx & 31) * 4;
            *(float4*)(&Bs[r][c]) = *(const float4*)(B + (long)(k0 + r) * N + col0 + c);
        }
        __syncthreads();
        #pragma unroll
        for (int k = 0; k < 16; k++) {
            float4 a0 = *(const float4*)(&As[k][ty * 8]);
            float4 a1 = *(const float4*)(&As[k][ty * 8 + 4]);
            float4 b0 = *(const float4*)(&Bs[k][tx * 8]);
            float4 b1 = *(const float4*)(&Bs[k][tx * 8 + 4]);
            float av[8] = {a0.x, a0.y, a0.z, a0.w, a1.x, a1.y, a1.z, a1.w};
            float bv[8] = {b0.x, b0.y, b0.z, b0.w, b1.x, b1.y, b1.z, b1.w};
            #pragma unroll
            for (int i = 0; i < 8; i++)
                #pragma unroll
                for (int j = 0; j < 8; j++)
                    acc[i][j] += av[i] * bv[j];
        }
        __syncthreads();
    }
    #pragma unroll
    for (int i = 0; i < 8; i++) {
        int gr = row0 + ty * 8 + i;
        if (gr < M) {
            *(float4*)(C + (long)gr * N + col0 + tx * 8)     =
                make_float4(acc[i][0], acc[i][1], acc[i][2], acc[i][3]);
            *(float4*)(C + (long)gr * N + col0 + tx * 8 + 4) =
                make_float4(acc[i][4], acc[i][5], acc[i][6], acc[i][7]);
        }
    }
}

// ================= SGEMM2 with fused ELU+bias on A ===========================
__global__ __launch_bounds__(256) void sgemm2_kernel(
    const float* __restrict__ A, const float* __restrict__ bias1,
    const float* __restrict__ B, float* __restrict__ C, int M) {
    const int K = D1, N = D2;
    __shared__ float As[16][128];
    __shared__ float Bs[16][64];
    int tid = threadIdx.x;
    int tx = tid & 15, ty = tid >> 4;
    int row0 = blockIdx.y * 128;
    float acc[8][4] = {};
    for (int k0 = 0; k0 < K; k0 += 16) {
        #pragma unroll
        for (int i = 0; i < 2; i++) {
            int idx = tid + i * 256;
            int r = idx >> 2, kc = (idx & 3) * 4;
            int gr = row0 + r;
            float4 v = make_float4(0.f, 0.f, 0.f, 0.f);
            if (gr < M) {
                v = *(const float4*)(A + (long)gr * K + k0 + kc);
                float4 bb = *(const float4*)(bias1 + k0 + kc);
                v.x += bb.x; v.y += bb.y; v.z += bb.z; v.w += bb.w;
                v.x = v.x > 0.f ? v.x : (__expf(v.x) - 1.f);
                v.y = v.y > 0.f ? v.y : (__expf(v.y) - 1.f);
                v.z = v.z > 0.f ? v.z : (__expf(v.z) - 1.f);
                v.w = v.w > 0.f ? v.w : (__expf(v.w) - 1.f);
            }
            As[kc + 0][r] = v.x; As[kc + 1][r] = v.y;
            As[kc + 2][r] = v.z; As[kc + 3][r] = v.w;
        }
        {
            int r = tid >> 4, c = (tid & 15) * 4;
            *(float4*)(&Bs[r][c]) = *(const float4*)(B + (long)(k0 + r) * N + c);
        }
        __syncthreads();
        #pragma unroll
        for (int k = 0; k < 16; k++) {
            float4 a0 = *(const float4*)(&As[k][ty * 8]);
            float4 a1 = *(const float4*)(&As[k][ty * 8 + 4]);
            float4 b0 = *(const float4*)(&Bs[k][tx * 4]);
            float av[8] = {a0.x, a0.y, a0.z, a0.w, a1.x, a1.y, a1.z, a1.w};
            float bv[4] = {b0.x, b0.y, b0.z, b0.w};
            #pragma unroll
            for (int i = 0; i < 8; i++)
                #pragma unroll
                for (int j = 0; j < 4; j++)
                    acc[i][j] += av[i] * bv[j];
        }
        __syncthreads();
    }
    #pragma unroll
    for (int i = 0; i < 8; i++) {
        int gr = row0 + ty * 8 + i;
        if (gr < M)
            *(float4*)(C + (long)gr * N + tx * 4) =
                make_float4(acc[i][0], acc[i][1], acc[i][2], acc[i][3]);
    }
}

// ================= per-node attention coefficients ===========================
__global__ void alpha1_kernel(const float* __restrict__ xl,
                              const float* __restrict__ att_s,
                              const float* __restrict__ att_d,
                              float* __restrict__ asrc, float* __restrict__ adst) {
    int w = (blockIdx.x * blockDim.x + threadIdx.x) >> 5;
    int lane = threadIdx.x & 31;
    if (w >= NNODES) return;
    const float* row = xl + (long)w * D1;
    float ps[H1] = {}, pd[H1] = {};
    #pragma unroll
    for (int j = 0; j < 8; j++) {
        int c = lane + j * 32;
        float v = row[c];
        int h = j >> 1;
        ps[h] += v * att_s[c];
        pd[h] += v * att_d[c];
    }
    #pragma unroll
    for (int off = 16; off; off >>= 1) {
        #pragma unroll
        for (int h = 0; h < H1; h++) {
            ps[h] += __shfl_xor_sync(0xFFFFFFFFu, ps[h], off);
            pd[h] += __shfl_xor_sync(0xFFFFFFFFu, pd[h], off);
        }
    }
    if (lane == 0) {
        *(float4*)(asrc + w * H1) = make_float4(ps[0], ps[1], ps[2], ps[3]);
        *(float4*)(adst + w * H1) = make_float4(pd[0], pd[1], pd[2], pd[3]);
    }
}

__global__ void alpha2_kernel(const float* __restrict__ xl,
                              const float* __restrict__ att_s,
                              const float* __restrict__ att_d,
                              float* __restrict__ asrc, float* __restrict__ adst) {
    int w = (blockIdx.x * blockDim.x + threadIdx.x) >> 5;
    int lane = threadIdx.x & 31;
    if (w >= NNODES) return;
    const float* row = xl + (long)w * D2;
    float v0 = row[lane], v1 = row[lane + 32];
    float ps = v0 * att_s[lane] + v1 * att_s[lane + 32];
    float pd = v0 * att_d[lane] + v1 * att_d[lane + 32];
    #pragma unroll
    for (int off = 16; off; off >>= 1) {
        ps += __shfl_xor_sync(0xFFFFFFFFu, ps, off);
        pd += __shfl_xor_sync(0xFFFFFFFFu, pd, off);
    }
    if (lane == 0) { asrc[w] = ps; adst[w] = pd; }
}

// ================= gather aggregation (no atomics) ===========================
// layer1: one warp per node; 256 ch = 2 float4 per lane.
// Edge (src, ex[4]) staged through shared memory per warp.
__global__ __launch_bounds__(256) void gather1_kernel(
    const int* __restrict__ rowptr, const int* __restrict__ srcs,
    const float* __restrict__ asrc, const float* __restrict__ adst,
    const float* __restrict__ xl, float* __restrict__ out) {
    __shared__ int   sm_s [8][32];
    __shared__ float sm_ex[8][4][32];
    int wslot = threadIdx.x >> 5;
    int node = blockIdx.x * 8 + wslot;
    if (node >= NNODES) return;
    int lane = threadIdx.x & 31;
    int beg = rowptr[node], end = rowptr[node + 1];
    float4 ad = *(const float4*)(adst + node * H1);
    int hmy = lane >> 3;
    float4 acc0 = make_float4(0.f, 0.f, 0.f, 0.f);
    float4 acc1 = make_float4(0.f, 0.f, 0.f, 0.f);
    float exsum = 0.f;
    for (int base = beg; base < end; base += 32) {
        int j = base + lane;
        if (j < end) {
            int sv = __ldg(srcs + j);
            float4 as = *(const float4*)(asrc + sv * H1);
            float v;
            sm_s[wslot][lane] = sv;
            v = as.x + ad.x; v = v > 0.f ? v : v * NEG_SLOPE; sm_ex[wslot][0][lane] = __expf(v);
            v = as.y + ad.y; v = v > 0.f ? v : v * NEG_SLOPE; sm_ex[wslot][1][lane] = __expf(v);
            v = as.z + ad.z; v = v > 0.f ? v : v * NEG_SLOPE; sm_ex[wslot][2][lane] = __expf(v);
            v = as.w + ad.w; v = v > 0.f ? v : v * NEG_SLOPE; sm_ex[wslot][3][lane] = __expf(v);
        }
        __syncwarp();
        int m = min(32, end - base);
        for (int t = 0; t < m; t++) {
            int   s   = sm_s[wslot][t];
            float exh = sm_ex[wslot][hmy][t];
            exsum += exh;
            const float* p = xl + (long)s * D1 + lane * 8;
            float4 va = __ldg((const float4*)p);
            float4 vb = __ldg((const float4*)(p + 4));
            acc0.x += exh * va.x; acc0.y += exh * va.y;
            acc0.z += exh * va.z; acc0.w += exh * va.w;
            acc1.x += exh * vb.x; acc1.y += exh * vb.y;
            acc1.z += exh * vb.z; acc1.w += exh * vb.w;
        }
        __syncwarp();
    }
    float inv = 1.f / exsum;
    float* o = out + (long)node * D1 + lane * 8;
    *(float4*)(o)     = make_float4(acc0.x * inv, acc0.y * inv, acc0.z * inv, acc0.w * inv);
    *(float4*)(o + 4) = make_float4(acc1.x * inv, acc1.y * inv, acc1.z * inv, acc1.w * inv);
}

// layer2: one warp per node; 64 ch = 2 floats per lane; writes final d_out
__global__ __launch_bounds__(256) void gather2_kernel(
    const int* __restrict__ rowptr, const int* __restrict__ srcs,
    const float* __restrict__ asrc, const float* __restrict__ adst,
    const float* __restrict__ xl, const float* __restrict__ b2,
    float* __restrict__ out) {
    int node = blockIdx.x * 8 + (threadIdx.x >> 5);
    if (node >= NNODES) return;
    int lane = threadIdx.x & 31;
    int beg = rowptr[node], end = rowptr[node + 1];
    float adv = adst[node];
    float acc0 = 0.f, acc1 = 0.f, exsum = 0.f;
    for (int base = beg; base < end; base += 32) {
        int j = base + lane;
        int sv = 0;
        float exv = 0.f;
        if (j < end) {
            sv = __ldg(srcs + j);
            float v = __ldg(asrc + sv) + adv;
            v = v > 0.f ? v : v * NEG_SLOPE;
            exv = __expf(v);
        }
        int m = min(32, end - base);
        for (int t = 0; t < m; t++) {
            int   s  = __shfl_sync(0xFFFFFFFFu, sv,  t);
            float ex = __shfl_sync(0xFFFFFFFFu, exv, t);
            exsum += ex;
            acc0 += ex * __ldg(xl + (long)s * D2 + lane);
            acc1 += ex * __ldg(xl + (long)s * D2 + lane + 32);
        }
    }
    float inv = 1.f / exsum;
    out[(long)node * D2 + lane]      = acc0 * inv + b2[lane];
    out[(long)node * D2 + lane + 32] = acc1 * inv + b2[lane + 32];
}

// ================= launch ====================================================
extern "C" void kernel_launch(void* const* d_in, const int* in_sizes, int n_in,
                              void* d_out, int out_size) {
    const float* x     = (const float*)d_in[0];
    const int*   ei    = (const int*)d_in[1];
    const float* W1    = (const float*)d_in[2];
    const float* at_s1 = (const float*)d_in[3];
    const float* at_d1 = (const float*)d_in[4];
    const float* b1    = (const float*)d_in[5];
    const float* W2    = (const float*)d_in[6];
    const float* at_s2 = (const float*)d_in[7];
    const float* at_d2 = (const float*)d_in[8];
    const float* b2    = (const float*)d_in[9];
    float* out = (float*)d_out;

    float *xl1, *agg1, *xl2, *as1, *ad1, *as2, *ad2;
    int *cnt, *rowptr, *wptr, *bsum, *boff, *srcs;
    cudaGetSymbolAddress((void**)&xl1,    g_xl1);
    cudaGetSymbolAddress((void**)&agg1,   g_agg1);
    cudaGetSymbolAddress((void**)&xl2,    g_xl2);
    cudaGetSymbolAddress((void**)&as1,    g_as1);
    cudaGetSymbolAddress((void**)&ad1,    g_ad1);
    cudaGetSymbolAddress((void**)&as2,    g_as2);
    cudaGetSymbolAddress((void**)&ad2,    g_ad2);
    cudaGetSymbolAddress((void**)&cnt,    g_cnt);
    cudaGetSymbolAddress((void**)&rowptr, g_rowptr);
    cudaGetSymbolAddress((void**)&wptr,   g_wptr);
    cudaGetSymbolAddress((void**)&bsum,   g_bsum);
    cudaGetSymbolAddress((void**)&boff,   g_boff);
    cudaGetSymbolAddress((void**)&srcs,   g_srcs);

    // ---- CSR build (by dst) ----
    zero_cnt<<<(NNODES + 255) / 256, 256>>>(cnt);
    hist_kernel<<<(ETOT + 255) / 256, 256>>>(ei, cnt);
    scan1_kernel<<<NBLK_SCAN, 256>>>(cnt, rowptr, bsum);
    scan2_kernel<<<1, 256>>>(bsum, boff);
    scan3_kernel<<<(NNODES + 255) / 256, 256>>>(rowptr, boff, wptr);
    scatter_kernel<<<(ETOT + 255) / 256, 256>>>(ei, wptr, srcs);

    // ---- layer 1 ----
    sgemm1_kernel<<<dim3(D1 / 128, (NNODES + 127) / 128), 256>>>(x, W1, xl1, NNODES);
    alpha1_kernel<<<(NNODES * 32 + 255) / 256, 256>>>(xl1, at_s1, at_d1, as1, ad1);
    gather1_kernel<<<(NNODES + 7) / 8, 256>>>(rowptr, srcs, as1, ad1, xl1, agg1);

    // ---- layer 2 (ELU + b1 fused into sgemm2 A-load; b2 fused into gather2) ----
    sgemm2_kernel<<<dim3(1, (NNODES + 127) / 128), 256>>>(agg1, b1, W2, xl2, NNODES);
    alpha2_kernel<<<(NNODES * 32 + 255) / 256, 256>>>(xl2, at_s2, at_d2, as2, ad2);
    gather2_kernel<<<(NNODES + 7) / 8, 256>>>(rowptr, srcs, as2, ad2, xl2, b2, out);
}

// round 7
// speedup vs baseline: 4.6574x; 1.0276x over previous
#include <cuda_runtime.h>

#define NNODES 50000
#define NEDGES 800000
#define ETOT   850000
#define FIN    128
#define H1     4
#define D1     256   // H1*C1
#define D2     64
#define DAGG   512   // H1*FIN  (per-head input-space aggregates)
#define NEG_SLOPE 0.2f
#define NBLK_SCAN 196   // ceil(50000/256)

// ---------------- scratch (static device globals) ---------------------------
static __device__ float g_aggx[NNODES * DAGG];  // per-head aggregated x (102 MB)
static __device__ float g_agg1[NNODES * D1];    // layer1 output (pre-ELU)
static __device__ float g_xl2 [NNODES * D2];    // h @ W2
static __device__ float g_ws1 [FIN * H1];       // W1h @ a_src  [128,4]
static __device__ float g_wd1 [FIN * H1];
static __device__ float g_as1 [NNODES * H1];
static __device__ float g_ad1 [NNODES * H1];
static __device__ float g_as2 [NNODES];
static __device__ float g_ad2 [NNODES];
static __device__ int   g_cnt [NNODES];
static __device__ int   g_rowptr[NNODES + 1];
static __device__ int   g_wptr[NNODES];
static __device__ int   g_bsum[256];
static __device__ int   g_boff[256];
static __device__ int   g_srcs[ETOT];

__device__ __forceinline__ void edge_nodes(const int* __restrict__ ei,
                                           int e, int& s, int& d) {
    if (e < NEDGES) { s = ei[e]; d = ei[NEDGES + e]; }
    else            { s = e - NEDGES; d = s; }
}

// ================= CSR build =================================================
__global__ void zero_cnt(int* __restrict__ cnt) {
    int i = blockIdx.x * blockDim.x + threadIdx.x;
    if (i < NNODES) cnt[i] = 0;
}

__global__ void hist_kernel(const int* __restrict__ ei, int* __restrict__ cnt) {
    int e = blockIdx.x * blockDim.x + threadIdx.x;
    if (e >= ETOT) return;
    int s, d; edge_nodes(ei, e, s, d);
    atomicAdd(&cnt[d], 1);
}

__global__ void scan1_kernel(const int* __restrict__ cnt,
                             int* __restrict__ rowptr, int* __restrict__ bsum) {
    __shared__ int sm[256];
    int tid = threadIdx.x;
    int i = blockIdx.x * 256 + tid;
    int val = (i < NNODES) ? cnt[i] : 0;
    sm[tid] = val;
    __syncthreads();
    #pragma unroll
    for (int off = 1; off < 256; off <<= 1) {
        int t = (tid >= off) ? sm[tid - off] : 0;
        __syncthreads();
        sm[tid] += t;
        __syncthreads();
    }
    if (i < NNODES) rowptr[i] = sm[tid] - val;
    if (tid == 255) bsum[blockIdx.x] = sm[tid];
}

__global__ void scan2_kernel(int* __restrict__ bsum, int* __restrict__ boff) {
    __shared__ int sm[256];
    int tid = threadIdx.x;
    int val = (tid < NBLK_SCAN) ? bsum[tid] : 0;
    sm[tid] = val;
    __syncthreads();
    #pragma unroll
    for (int off = 1; off < 256; off <<= 1) {
        int t = (tid >= off) ? sm[tid - off] : 0;
        __syncthreads();
        sm[tid] += t;
        __syncthreads();
    }
    boff[tid] = sm[tid] - val;
}

__global__ void scan3_kernel(int* __restrict__ rowptr, const int* __restrict__ boff,
                             int* __restrict__ wptr) {
    int i = blockIdx.x * blockDim.x + threadIdx.x;
    if (i < NNODES) {
        int r = rowptr[i] + boff[i >> 8];
        rowptr[i] = r;
        wptr[i]   = r;
    }
    if (i == 0) rowptr[NNODES] = ETOT;
}

__global__ void scatter_kernel(const int* __restrict__ ei, int* __restrict__ wptr,
                               int* __restrict__ srcs) {
    int e = blockIdx.x * blockDim.x + threadIdx.x;
    if (e >= ETOT) return;
    int s, d; edge_nodes(ei, e, s, d);
    srcs[atomicAdd(&wptr[d], 1)] = s;
}

// ================= layer-1 attention weight precompute =======================
// ws[c,h] = sum_j W1[c, h*64+j] * a_src[h,j]   (and same for dst)
__global__ void w1prep_kernel(const float* __restrict__ W1,
                              const float* __restrict__ a_s,
                              const float* __restrict__ a_d,
                              float* __restrict__ ws, float* __restrict__ wd) {
    int t = threadIdx.x;              // 512 threads
    int c = t >> 2, h = t & 3;
    float accs = 0.f, accd = 0.f;
    #pragma unroll 8
    for (int j = 0; j < 64; j++) {
        float w = W1[c * D1 + h * 64 + j];
        accs += w * a_s[h * 64 + j];
        accd += w * a_d[h * 64 + j];
    }
    ws[c * 4 + h] = accs;
    wd[c * 4 + h] = accd;
}

// ================= per-node attention coefficients ===========================
// layer1 from raw x: as1[n,h] = x[n] . ws[:,h]
__global__ void alpha1_kernel(const float* __restrict__ x,
                              const float* __restrict__ ws,
                              const float* __restrict__ wd,
                              float* __restrict__ asrc, float* __restrict__ adst) {
    int w = (blockIdx.x * blockDim.x + threadIdx.x) >> 5;
    int lane = threadIdx.x & 31;
    if (w >= NNODES) return;
    const float* row = x + (long)w * FIN;
    float ps[4] = {}, pd[4] = {};
    #pragma unroll
    for (int j = 0; j < 4; j++) {
        int c = lane + j * 32;
        float v = row[c];
        float4 a = *(const float4*)(ws + c * 4);
        float4 b = *(const float4*)(wd + c * 4);
        ps[0] += v * a.x; ps[1] += v * a.y; ps[2] += v * a.z; ps[3] += v * a.w;
        pd[0] += v * b.x; pd[1] += v * b.y; pd[2] += v * b.z; pd[3] += v * b.w;
    }
    #pragma unroll
    for (int off = 16; off; off >>= 1) {
        #pragma unroll
        for (int h = 0; h < 4; h++) {
            ps[h] += __shfl_xor_sync(0xFFFFFFFFu, ps[h], off);
            pd[h] += __shfl_xor_sync(0xFFFFFFFFu, pd[h], off);
        }
    }
    if (lane == 0) {
        *(float4*)(asrc + w * 4) = make_float4(ps[0], ps[1], ps[2], ps[3]);
        *(float4*)(adst + w * 4) = make_float4(pd[0], pd[1], pd[2], pd[3]);
    }
}

__global__ void alpha2_kernel(const float* __restrict__ xl,
                              const float* __restrict__ att_s,
                              const float* __restrict__ att_d,
                              float* __restrict__ asrc, float* __restrict__ adst) {
    int w = (blockIdx.x * blockDim.x + threadIdx.x) >> 5;
    int lane = threadIdx.x & 31;
    if (w >= NNODES) return;
    const float* row = xl + (long)w * D2;
    float v0 = row[lane], v1 = row[lane + 32];
    float ps = v0 * att_s[lane] + v1 * att_s[lane + 32];
    float pd = v0 * att_d[lane] + v1 * att_d[lane + 32];
    #pragma unroll
    for (int off = 16; off; off >>= 1) {
        ps += __shfl_xor_sync(0xFFFFFFFFu, ps, off);
        pd += __shfl_xor_sync(0xFFFFFFFFu, pd, off);
    }
    if (lane == 0) { asrc[w] = ps; adst[w] = pd; }
}

// ================= gather layer1: aggregate raw x per head ===================
// warp per node; lane covers 4 ch of 128; 4 head accumulators.
// out aggx[n, h*128 + c] = (sum_e ex_h * x[s_e, c]) / sum_e ex_h
__global__ __launch_bounds__(256) void gather1_kernel(
    const int* __restrict__ rowptr, const int* __restrict__ srcs,
    const float* __restrict__ asrc, const float* __restrict__ adst,
    const float* __restrict__ x, float* __restrict__ aggx) {
    __shared__ int    sm_s [8][32];
    __shared__ float4 sm_ex[8][32];
    int wslot = threadIdx.x >> 5;
    int node = blockIdx.x * 8 + wslot;
    if (node >= NNODES) return;
    int lane = threadIdx.x & 31;
    int beg = rowptr[node], end = rowptr[node + 1];
    float4 ad = *(const float4*)(adst + node * 4);
    float acc[4][4] = {};
    float exsum[4] = {};
    for (int base = beg; base < end; base += 32) {
        int j = base + lane;
        if (j < end) {
            int sv = __ldg(srcs + j);
            float4 as = *(const float4*)(asrc + sv * 4);
            float v;
            float4 ex;
            v = as.x + ad.x; v = v > 0.f ? v : v * NEG_SLOPE; ex.x = __expf(v);
            v = as.y + ad.y; v = v > 0.f ? v : v * NEG_SLOPE; ex.y = __expf(v);
            v = as.z + ad.z; v = v > 0.f ? v : v * NEG_SLOPE; ex.z = __expf(v);
            v = as.w + ad.w; v = v > 0.f ? v : v * NEG_SLOPE; ex.w = __expf(v);
            sm_s[wslot][lane]  = sv;
            sm_ex[wslot][lane] = ex;
        }
        __syncwarp();
        int m = min(32, end - base);
        for (int t = 0; t < m; t++) {
            int    s  = sm_s[wslot][t];
            float4 ex = sm_ex[wslot][t];
            exsum[0] += ex.x; exsum[1] += ex.y; exsum[2] += ex.z; exsum[3] += ex.w;
            float4 v = __ldg((const float4*)(x + (long)s * FIN + lane * 4));
            acc[0][0] += ex.x * v.x; acc[0][1] += ex.x * v.y;
            acc[0][2] += ex.x * v.z; acc[0][3] += ex.x * v.w;
            acc[1][0] += ex.y * v.x; acc[1][1] += ex.y * v.y;
            acc[1][2] += ex.y * v.z; acc[1][3] += ex.y * v.w;
            acc[2][0] += ex.z * v.x; acc[2][1] += ex.z * v.y;
            acc[2][2] += ex.z * v.z; acc[2][3] += ex.z * v.w;
            acc[3][0] += ex.w * v.x; acc[3][1] += ex.w * v.y;
            acc[3][2] += ex.w * v.z; acc[3][3] += ex.w * v.w;
        }
        __syncwarp();
    }
    float* o = aggx + (long)node * DAGG + lane * 4;
    #pragma unroll
    for (int h = 0; h < 4; h++) {
        float inv = 1.f / exsum[h];
        *(float4*)(o + h * FIN) = make_float4(acc[h][0] * inv, acc[h][1] * inv,
                                              acc[h][2] * inv, acc[h][3] * inv);
    }
}

// ================= per-head GEMM: agg1[n, h*64+j] = aggx[n,h,:] @ W1h ========
// BM=128 BN=64 BK=16, 256 threads, 8x4 per thread; blockIdx.z = head
__global__ __launch_bounds__(256) void sgemm_h_kernel(
    const float* __restrict__ A,   // aggx, row stride DAGG
    const float* __restrict__ B,   // W1, row stride D1
    float* __restrict__ C,         // agg1, row stride D1
    int M) {
    const int K = FIN;
    int h = blockIdx.z;
    const float* Ah = A + h * FIN;
    const float* Bh = B + h * 64;
    float*       Ch = C + h * 64;
    __shared__ float As[16][128];
    __shared__ float Bs[16][64];
    int tid = threadIdx.x;
    int tx = tid & 15, ty = tid >> 4;
    int row0 = blockIdx.y * 128;
    float acc[8][4] = {};
    for (int k0 = 0; k0 < K; k0 += 16) {
        #pragma unroll
        for (int i = 0; i < 2; i++) {
            int idx = tid + i * 256;
            int r = idx >> 2, kc = (idx & 3) * 4;
            int gr = row0 + r;
            float4 v = make_float4(0.f, 0.f, 0.f, 0.f);
            if (gr < M) v = *(const float4*)(Ah + (long)gr * DAGG + k0 + kc);
            As[kc + 0][r] = v.x; As[kc + 1][r] = v.y;
            As[kc + 2][r] = v.z; As[kc + 3][r] = v.w;
        }
        {
            int r = tid >> 4, c = (tid & 15) * 4;
            *(float4*)(&Bs[r][c]) = *(const float4*)(Bh + (long)(k0 + r) * D1 + c);
        }
        __syncthreads();
        #pragma unroll
        for (int k = 0; k < 16; k++) {
            float4 a0 = *(const float4*)(&As[k][ty * 8]);
            float4 a1 = *(const float4*)(&As[k][ty * 8 + 4]);
            float4 b0 = *(const float4*)(&Bs[k][tx * 4]);
            float av[8] = {a0.x, a0.y, a0.z, a0.w, a1.x, a1.y, a1.z, a1.w};
            float bv[4] = {b0.x, b0.y, b0.z, b0.w};
            #pragma unroll
            for (int i = 0; i < 8; i++)
                #pragma unroll
                for (int j = 0; j < 4; j++)
                    acc[i][j] += av[i] * bv[j];
        }
        __syncthreads();
    }
    #pragma unroll
    for (int i = 0; i < 8; i++) {
        int gr = row0 + ty * 8 + i;
        if (gr < M)
            *(float4*)(Ch + (long)gr * D1 + tx * 4) =
                make_float4(acc[i][0], acc[i][1], acc[i][2], acc[i][3]);
    }
}

// ================= SGEMM2 with fused ELU+bias on A ===========================
__global__ __launch_bounds__(256) void sgemm2_kernel(
    const float* __restrict__ A, const float* __restrict__ bias1,
    const float* __restrict__ B, float* __restrict__ C, int M) {
    const int K = D1, N = D2;
    __shared__ float As[16][128];
    __shared__ float Bs[16][64];
    int tid = threadIdx.x;
    int tx = tid & 15, ty = tid >> 4;
    int row0 = blockIdx.y * 128;
    float acc[8][4] = {};
    for (int k0 = 0; k0 < K; k0 += 16) {
        #pragma unroll
        for (int i = 0; i < 2; i++) {
            int idx = tid + i * 256;
            int r = idx >> 2, kc = (idx & 3) * 4;
            int gr = row0 + r;
            float4 v = make_float4(0.f, 0.f, 0.f, 0.f);
            if (gr < M) {
                v = *(const float4*)(A + (long)gr * K + k0 + kc);
                float4 bb = *(const float4*)(bias1 + k0 + kc);
                v.x += bb.x; v.y += bb.y; v.z += bb.z; v.w += bb.w;
                v.x = v.x > 0.f ? v.x : (__expf(v.x) - 1.f);
                v.y = v.y > 0.f ? v.y : (__expf(v.y) - 1.f);
                v.z = v.z > 0.f ? v.z : (__expf(v.z) - 1.f);
                v.w = v.w > 0.f ? v.w : (__expf(v.w) - 1.f);
            }
            As[kc + 0][r] = v.x; As[kc + 1][r] = v.y;
            As[kc + 2][r] = v.z; As[kc + 3][r] = v.w;
        }
        {
            int r = tid >> 4, c = (tid & 15) * 4;
            *(float4*)(&Bs[r][c]) = *(const float4*)(B + (long)(k0 + r) * N + c);
        }
        __syncthreads();
        #pragma unroll
        for (int k = 0; k < 16; k++) {
            float4 a0 = *(const float4*)(&As[k][ty * 8]);
            float4 a1 = *(const float4*)(&As[k][ty * 8 + 4]);
            float4 b0 = *(const float4*)(&Bs[k][tx * 4]);
            float av[8] = {a0.x, a0.y, a0.z, a0.w, a1.x, a1.y, a1.z, a1.w};
            float bv[4] = {b0.x, b0.y, b0.z, b0.w};
            #pragma unroll
            for (int i = 0; i < 8; i++)
                #pragma unroll
                for (int j = 0; j < 4; j++)
                    acc[i][j] += av[i] * bv[j];
        }
        __syncthreads();
    }
    #pragma unroll
    for (int i = 0; i < 8; i++) {
        int gr = row0 + ty * 8 + i;
        if (gr < M)
            *(float4*)(C + (long)gr * N + tx * 4) =
                make_float4(acc[i][0], acc[i][1], acc[i][2], acc[i][3]);
    }
}

// ================= gather layer2 (unchanged, writes final d_out) =============
__global__ __launch_bounds__(256) void gather2_kernel(
    const int* __restrict__ rowptr, const int* __restrict__ srcs,
    const float* __restrict__ asrc, const float* __restrict__ adst,
    const float* __restrict__ xl, const float* __restrict__ b2,
    float* __restrict__ out) {
    int node = blockIdx.x * 8 + (threadIdx.x >> 5);
    if (node >= NNODES) return;
    int lane = threadIdx.x & 31;
    int beg = rowptr[node], end = rowptr[node + 1];
    float adv = adst[node];
    float acc0 = 0.f, acc1 = 0.f, exsum = 0.f;
    for (int base = beg; base < end; base += 32) {
        int j = base + lane;
        int sv = 0;
        float exv = 0.f;
        if (j < end) {
            sv = __ldg(srcs + j);
            float v = __ldg(asrc + sv) + adv;
            v = v > 0.f ? v : v * NEG_SLOPE;
            exv = __expf(v);
        }
        int m = min(32, end - base);
        for (int t = 0; t < m; t++) {
            int   s  = __shfl_sync(0xFFFFFFFFu, sv,  t);
            float ex = __shfl_sync(0xFFFFFFFFu, exv, t);
            exsum += ex;
            acc0 += ex * __ldg(xl + (long)s * D2 + lane);
            acc1 += ex * __ldg(xl + (long)s * D2 + lane + 32);
        }
    }
    float inv = 1.f / exsum;
    out[(long)node * D2 + lane]      = acc0 * inv + b2[lane];
    out[(long)node * D2 + lane + 32] = acc1 * inv + b2[lane + 32];
}

// ================= launch ====================================================
extern "C" void kernel_launch(void* const* d_in, const int* in_sizes, int n_in,
                              void* d_out, int out_size) {
    const float* x     = (const float*)d_in[0];
    const int*   ei    = (const int*)d_in[1];
    const float* W1    = (const float*)d_in[2];
    const float* at_s1 = (const float*)d_in[3];
    const float* at_d1 = (const float*)d_in[4];
    const float* b1    = (const float*)d_in[5];
    const float* W2    = (const float*)d_in[6];
    const float* at_s2 = (const float*)d_in[7];
    const float* at_d2 = (const float*)d_in[8];
    const float* b2    = (const float*)d_in[9];
    float* out = (float*)d_out;

    float *aggx, *agg1, *xl2, *ws1, *wd1, *as1, *ad1, *as2, *ad2;
    int *cnt, *rowptr, *wptr, *bsum, *boff, *srcs;
    cudaGetSymbolAddress((void**)&aggx,   g_aggx);
    cudaGetSymbolAddress((void**)&agg1,   g_agg1);
    cudaGetSymbolAddress((void**)&xl2,    g_xl2);
    cudaGetSymbolAddress((void**)&ws1,    g_ws1);
    cudaGetSymbolAddress((void**)&wd1,    g_wd1);
    cudaGetSymbolAddress((void**)&as1,    g_as1);
    cudaGetSymbolAddress((void**)&ad1,    g_ad1);
    cudaGetSymbolAddress((void**)&as2,    g_as2);
    cudaGetSymbolAddress((void**)&ad2,    g_ad2);
    cudaGetSymbolAddress((void**)&cnt,    g_cnt);
    cudaGetSymbolAddress((void**)&rowptr, g_rowptr);
    cudaGetSymbolAddress((void**)&wptr,   g_wptr);
    cudaGetSymbolAddress((void**)&bsum,   g_bsum);
    cudaGetSymbolAddress((void**)&boff,   g_boff);
    cudaGetSymbolAddress((void**)&srcs,   g_srcs);

    // ---- CSR build (by dst) ----
    zero_cnt<<<(NNODES + 255) / 256, 256>>>(cnt);
    hist_kernel<<<(ETOT + 255) / 256, 256>>>(ei, cnt);
    scan1_kernel<<<NBLK_SCAN, 256>>>(cnt, rowptr, bsum);
    scan2_kernel<<<1, 256>>>(bsum, boff);
    scan3_kernel<<<(NNODES + 255) / 256, 256>>>(rowptr, boff, wptr);
    scatter_kernel<<<(ETOT + 255) / 256, 256>>>(ei, wptr, srcs);

    // ---- layer 1: alpha from raw x, gather in input space, then per-head GEMM
    w1prep_kernel<<<1, 512>>>(W1, at_s1, at_d1, ws1, wd1);
    alpha1_kernel<<<(NNODES * 32 + 255) / 256, 256>>>(x, ws1, wd1, as1, ad1);
    gather1_kernel<<<(NNODES + 7) / 8, 256>>>(rowptr, srcs, as1, ad1, x, aggx);
    sgemm_h_kernel<<<dim3(1, (NNODES + 127) / 128, H1), 256>>>(aggx, W1, agg1, NNODES);

    // ---- layer 2 (ELU + b1 fused into sgemm2 A-load; b2 fused into gather2) ----
    sgemm2_kernel<<<dim3(1, (NNODES + 127) / 128), 256>>>(agg1, b1, W2, xl2, NNODES);
    alpha2_kernel<<<(NNODES * 32 + 255) / 256, 256>>>(xl2, at_s2, at_d2, as2, ad2);
    gather2_kernel<<<(NNODES + 7) / 8, 256>>>(rowptr, srcs, as2, ad2, xl2, b2, out);
}

// round 8
// speedup vs baseline: 5.9857x; 1.2852x over previous
#include <cuda_runtime.h>
#include <cstdint>

#define NNODES 50000
#define NEDGES 800000
#define ETOT   850000
#define FIN    128
#define H1     4
#define D1     256   // H1*C1
#define D2     64
#define DAGG   512   // H1*FIN
#define NEG_SLOPE 0.2f
#define NBLK_SCAN 196   // ceil(50000/256)

// ---------------- scratch (static device globals) ---------------------------
static __device__ float g_aggx[NNODES * DAGG];
static __device__ float g_agg1[NNODES * D1];
static __device__ float g_xl2 [NNODES * D2];
static __device__ float g_ws1 [FIN * H1];
static __device__ float g_wd1 [FIN * H1];
static __device__ float g_as1 [NNODES * H1];
static __device__ float g_ad1 [NNODES * H1];
static __device__ float g_as2 [NNODES];
static __device__ float g_ad2 [NNODES];
static __device__ int   g_cnt [NNODES];
static __device__ int   g_rowptr[NNODES + 1];
static __device__ int   g_wptr[NNODES];
static __device__ int   g_bsum[256];
static __device__ int   g_boff[256];
static __device__ int   g_srcs[ETOT];

__device__ __forceinline__ void edge_nodes(const int* __restrict__ ei,
                                           int e, int& s, int& d) {
    if (e < NEDGES) { s = ei[e]; d = ei[NEDGES + e]; }
    else            { s = e - NEDGES; d = s; }
}

__device__ __forceinline__ uint32_t f2tf(float f) {
    uint32_t u;
    asm("cvt.rna.tf32.f32 %0, %1;" : "=r"(u) : "f"(f));
    return u;
}

__device__ __forceinline__ void mma_tf32(float c[4], const uint32_t a[4],
                                         const uint32_t b[2]) {
    asm volatile(
        "mma.sync.aligned.m16n8k8.row.col.f32.tf32.tf32.f32 "
        "{%0,%1,%2,%3}, {%4,%5,%6,%7}, {%8,%9}, {%0,%1,%2,%3};"
        : "+f"(c[0]), "+f"(c[1]), "+f"(c[2]), "+f"(c[3])
        : "r"(a[0]), "r"(a[1]), "r"(a[2]), "r"(a[3]), "r"(b[0]), "r"(b[1]));
}

// ================= CSR build =================================================
__global__ void zero_cnt(int* __restrict__ cnt) {
    int i = blockIdx.x * blockDim.x + threadIdx.x;
    if (i < NNODES) cnt[i] = 0;
}

__global__ void hist_kernel(const int* __restrict__ ei, int* __restrict__ cnt) {
    int e = blockIdx.x * blockDim.x + threadIdx.x;
    if (e >= ETOT) return;
    int s, d; edge_nodes(ei, e, s, d);
    atomicAdd(&cnt[d], 1);
}

__global__ void scan1_kernel(const int* __restrict__ cnt,
                             int* __restrict__ rowptr, int* __restrict__ bsum) {
    __shared__ int sm[256];
    int tid = threadIdx.x;
    int i = blockIdx.x * 256 + tid;
    int val = (i < NNODES) ? cnt[i] : 0;
    sm[tid] = val;
    __syncthreads();
    #pragma unroll
    for (int off = 1; off < 256; off <<= 1) {
        int t = (tid >= off) ? sm[tid - off] : 0;
        __syncthreads();
        sm[tid] += t;
        __syncthreads();
    }
    if (i < NNODES) rowptr[i] = sm[tid] - val;
    if (tid == 255) bsum[blockIdx.x] = sm[tid];
}

__global__ void scan2_kernel(int* __restrict__ bsum, int* __restrict__ boff) {
    __shared__ int sm[256];
    int tid = threadIdx.x;
    int val = (tid < NBLK_SCAN) ? bsum[tid] : 0;
    sm[tid] = val;
    __syncthreads();
    #pragma unroll
    for (int off = 1; off < 256; off <<= 1) {
        int t = (tid >= off) ? sm[tid - off] : 0;
        __syncthreads();
        sm[tid] += t;
        __syncthreads();
    }
    boff[tid] = sm[tid] - val;
}

__global__ void scan3_kernel(int* __restrict__ rowptr, const int* __restrict__ boff,
                             int* __restrict__ wptr) {
    int i = blockIdx.x * blockDim.x + threadIdx.x;
    if (i < NNODES) {
        int r = rowptr[i] + boff[i >> 8];
        rowptr[i] = r;
        wptr[i]   = r;
    }
    if (i == 0) rowptr[NNODES] = ETOT;
}

__global__ void scatter_kernel(const int* __restrict__ ei, int* __restrict__ wptr,
                               int* __restrict__ srcs) {
    int e = blockIdx.x * blockDim.x + threadIdx.x;
    if (e >= ETOT) return;
    int s, d; edge_nodes(ei, e, s, d);
    srcs[atomicAdd(&wptr[d], 1)] = s;
}

// ================= layer-1 attention weight precompute =======================
__global__ void w1prep_kernel(const float* __restrict__ W1,
                              const float* __restrict__ a_s,
                              const float* __restrict__ a_d,
                              float* __restrict__ ws, float* __restrict__ wd) {
    int t = threadIdx.x;              // 512 threads
    int c = t >> 2, h = t & 3;
    float accs = 0.f, accd = 0.f;
    #pragma unroll 8
    for (int j = 0; j < 64; j++) {
        float w = W1[c * D1 + h * 64 + j];
        accs += w * a_s[h * 64 + j];
        accd += w * a_d[h * 64 + j];
    }
    ws[c * 4 + h] = accs;
    wd[c * 4 + h] = accd;
}

// ================= per-node attention coefficients ===========================
__global__ void alpha1_kernel(const float* __restrict__ x,
                              const float* __restrict__ ws,
                              const float* __restrict__ wd,
                              float* __restrict__ asrc, float* __restrict__ adst) {
    int w = (blockIdx.x * blockDim.x + threadIdx.x) >> 5;
    int lane = threadIdx.x & 31;
    if (w >= NNODES) return;
    const float* row = x + (long)w * FIN;
    float ps[4] = {}, pd[4] = {};
    #pragma unroll
    for (int j = 0; j < 4; j++) {
        int c = lane + j * 32;
        float v = row[c];
        float4 a = *(const float4*)(ws + c * 4);
        float4 b = *(const float4*)(wd + c * 4);
        ps[0] += v * a.x; ps[1] += v * a.y; ps[2] += v * a.z; ps[3] += v * a.w;
        pd[0] += v * b.x; pd[1] += v * b.y; pd[2] += v * b.z; pd[3] += v * b.w;
    }
    #pragma unroll
    for (int off = 16; off; off >>= 1) {
        #pragma unroll
        for (int h = 0; h < 4; h++) {
            ps[h] += __shfl_xor_sync(0xFFFFFFFFu, ps[h], off);
            pd[h] += __shfl_xor_sync(0xFFFFFFFFu, pd[h], off);
        }
    }
    if (lane == 0) {
        *(float4*)(asrc + w * 4) = make_float4(ps[0], ps[1], ps[2], ps[3]);
        *(float4*)(adst + w * 4) = make_float4(pd[0], pd[1], pd[2], pd[3]);
    }
}

__global__ void alpha2_kernel(const float* __restrict__ xl,
                              const float* __restrict__ att_s,
                              const float* __restrict__ att_d,
                              float* __restrict__ asrc, float* __restrict__ adst) {
    int w = (blockIdx.x * blockDim.x + threadIdx.x) >> 5;
    int lane = threadIdx.x & 31;
    if (w >= NNODES) return;
    const float* row = xl + (long)w * D2;
    float v0 = row[lane], v1 = row[lane + 32];
    float ps = v0 * att_s[lane] + v1 * att_s[lane + 32];
    float pd = v0 * att_d[lane] + v1 * att_d[lane + 32];
    #pragma unroll
    for (int off = 16; off; off >>= 1) {
        ps += __shfl_xor_sync(0xFFFFFFFFu, ps, off);
        pd += __shfl_xor_sync(0xFFFFFFFFu, pd, off);
    }
    if (lane == 0) { asrc[w] = ps; adst[w] = pd; }
}

// ================= gather layer1 (input space) ===============================
__global__ __launch_bounds__(256) void gather1_kernel(
    const int* __restrict__ rowptr, const int* __restrict__ srcs,
    const float* __restrict__ asrc, const float* __restrict__ adst,
    const float* __restrict__ x, float* __restrict__ aggx) {
    __shared__ int    sm_s [8][32];
    __shared__ float4 sm_ex[8][32];
    int wslot = threadIdx.x >> 5;
    int node = blockIdx.x * 8 + wslot;
    if (node >= NNODES) return;
    int lane = threadIdx.x & 31;
    int beg = rowptr[node], end = rowptr[node + 1];
    float4 ad = *(const float4*)(adst + node * 4);
    float acc[4][4] = {};
    float exsum[4] = {};
    for (int base = beg; base < end; base += 32) {
        int j = base + lane;
        if (j < end) {
            int sv = __ldg(srcs + j);
            float4 as = *(const float4*)(asrc + sv * 4);
            float v;
            float4 ex;
            v = as.x + ad.x; v = v > 0.f ? v : v * NEG_SLOPE; ex.x = __expf(v);
            v = as.y + ad.y; v = v > 0.f ? v : v * NEG_SLOPE; ex.y = __expf(v);
            v = as.z + ad.z; v = v > 0.f ? v : v * NEG_SLOPE; ex.z = __expf(v);
            v = as.w + ad.w; v = v > 0.f ? v : v * NEG_SLOPE; ex.w = __expf(v);
            sm_s[wslot][lane]  = sv;
            sm_ex[wslot][lane] = ex;
        }
        __syncwarp();
        int m = min(32, end - base);
        for (int t = 0; t < m; t++) {
            int    s  = sm_s[wslot][t];
            float4 ex = sm_ex[wslot][t];
            exsum[0] += ex.x; exsum[1] += ex.y; exsum[2] += ex.z; exsum[3] += ex.w;
            float4 v = __ldg((const float4*)(x + (long)s * FIN + lane * 4));
            acc[0][0] += ex.x * v.x; acc[0][1] += ex.x * v.y;
            acc[0][2] += ex.x * v.z; acc[0][3] += ex.x * v.w;
            acc[1][0] += ex.y * v.x; acc[1][1] += ex.y * v.y;
            acc[1][2] += ex.y * v.z; acc[1][3] += ex.y * v.w;
            acc[2][0] += ex.z * v.x; acc[2][1] += ex.z * v.y;
            acc[2][2] += ex.z * v.z; acc[2][3] += ex.z * v.w;
            acc[3][0] += ex.w * v.x; acc[3][1] += ex.w * v.y;
            acc[3][2] += ex.w * v.z; acc[3][3] += ex.w * v.w;
        }
        __syncwarp();
    }
    float* o = aggx + (long)node * DAGG + lane * 4;
    #pragma unroll
    for (int h = 0; h < 4; h++) {
        float inv = 1.f / exsum[h];
        *(float4*)(o + h * FIN) = make_float4(acc[h][0] * inv, acc[h][1] * inv,
                                              acc[h][2] * inv, acc[h][3] * inv);
    }
}

// ================= tf32 GEMM core (BM=128, BN=64, BK=32, 8 warps) ============
// As[128][36], Bs[32][72] in tf32 bits; warp (wm,wn) computes 32x32.
struct GemmSmem {
    uint32_t As[128][36];
    uint32_t Bs[32][72];
};

__device__ __forceinline__ void gemm_tiles_mma(
    GemmSmem& S, int lane, int wm, int wn, float acc[2][4][4]) {
    #pragma unroll
    for (int k8 = 0; k8 < 4; k8++) {
        int kb = k8 * 8;
        uint32_t a[2][4];
        #pragma unroll
        for (int mt = 0; mt < 2; mt++) {
            int row = wm * 32 + mt * 16 + (lane >> 2);
            int col = kb + (lane & 3);
            a[mt][0] = S.As[row][col];
            a[mt][1] = S.As[row + 8][col];
            a[mt][2] = S.As[row][col + 4];
            a[mt][3] = S.As[row + 8][col + 4];
        }
        uint32_t b[4][2];
        #pragma unroll
        for (int nt = 0; nt < 4; nt++) {
            int kk = kb + (lane & 3);
            int nn = wn * 32 + nt * 8 + (lane >> 2);
            b[nt][0] = S.Bs[kk][nn];
            b[nt][1] = S.Bs[kk + 4][nn];
        }
        #pragma unroll
        for (int mt = 0; mt < 2; mt++)
            #pragma unroll
            for (int nt = 0; nt < 4; nt++)
                mma_tf32(acc[mt][nt], a[mt], b[nt]);
    }
}

__device__ __forceinline__ void gemm_store_c(
    float* C, int ldc, int M, int row0, int lane, int wm, int wn,
    float acc[2][4][4]) {
    #pragma unroll
    for (int mt = 0; mt < 2; mt++) {
        #pragma unroll
        for (int nt = 0; nt < 4; nt++) {
            int r0 = row0 + wm * 32 + mt * 16 + (lane >> 2);
            int c0 = wn * 32 + nt * 8 + (lane & 3) * 2;
            if (r0 < M)
                *(float2*)(C + (long)r0 * ldc + c0) =
                    make_float2(acc[mt][nt][0], acc[mt][nt][1]);
            if (r0 + 8 < M)
                *(float2*)(C + (long)(r0 + 8) * ldc + c0) =
                    make_float2(acc[mt][nt][2], acc[mt][nt][3]);
        }
    }
}

// per-head layer-1 GEMM: C[., h*64+n] = aggx[., h*128+k] @ W1[k, h*64+n]
__global__ __launch_bounds__(256) void tf32_gemm_h(
    const float* __restrict__ A, const float* __restrict__ B,
    float* __restrict__ C, int M) {
    __shared__ GemmSmem S;
    int tid = threadIdx.x, lane = tid & 31, wid = tid >> 5;
    int wm = wid >> 1, wn = wid & 1;
    int row0 = blockIdx.y * 128;
    int h = blockIdx.z;
    const float* Ah = A + h * FIN;   // lda DAGG
    const float* Bh = B + h * 64;    // ldb D1
    float*       Ch = C + h * 64;    // ldc D1
    float acc[2][4][4] = {};
    for (int k0 = 0; k0 < FIN; k0 += 32) {
        __syncthreads();
        {   // A tile 128x32: 2 threads/row, 16 floats each
            int r = tid >> 1, kc = (tid & 1) * 16;
            int gr = row0 + r;
            #pragma unroll
            for (int i = 0; i < 4; i++) {
                float4 v = make_float4(0.f, 0.f, 0.f, 0.f);
                if (gr < M)
                    v = *(const float4*)(Ah + (long)gr * DAGG + k0 + kc + i * 4);
                uint4 u = make_uint4(f2tf(v.x), f2tf(v.y), f2tf(v.z), f2tf(v.w));
                *(uint4*)(&S.As[r][kc + i * 4]) = u;
            }
        }
        {   // B tile 32x64: 8 threads/row, 8 floats each
            int k = tid >> 3, n0 = (tid & 7) * 8;
            #pragma unroll
            for (int i = 0; i < 2; i++) {
                float4 v = *(const float4*)(Bh + (long)(k0 + k) * D1 + n0 + i * 4);
                uint4 u = make_uint4(f2tf(v.x), f2tf(v.y), f2tf(v.z), f2tf(v.w));
                *(uint4*)(&S.Bs[k][n0 + i * 4]) = u;
            }
        }
        __syncthreads();
        gemm_tiles_mma(S, lane, wm, wn, acc);
    }
    gemm_store_c(Ch, D1, M, row0, lane, wm, wn, acc);
}

// layer-2 GEMM with fused bias1+ELU on A: C = ELU(A+b1) @ W2
__global__ __launch_bounds__(256) void tf32_gemm2(
    const float* __restrict__ A, const float* __restrict__ bias1,
    const float* __restrict__ B, float* __restrict__ C, int M) {
    __shared__ GemmSmem S;
    int tid = threadIdx.x, lane = tid & 31, wid = tid >> 5;
    int wm = wid >> 1, wn = wid & 1;
    int row0 = blockIdx.y * 128;
    float acc[2][4][4] = {};
    for (int k0 = 0; k0 < D1; k0 += 32) {
        __syncthreads();
        {
            int r = tid >> 1, kc = (tid & 1) * 16;
            int gr = row0 + r;
            #pragma unroll
            for (int i = 0; i < 4; i++) {
                float4 v = make_float4(0.f, 0.f, 0.f, 0.f);
                if (gr < M) {
                    v = *(const float4*)(A + (long)gr * D1 + k0 + kc + i * 4);
                    float4 bb = *(const float4*)(bias1 + k0 + kc + i * 4);
                    v.x += bb.x; v.y += bb.y; v.z += bb.z; v.w += bb.w;
                    v.x = v.x > 0.f ? v.x : (__expf(v.x) - 1.f);
                    v.y = v.y > 0.f ? v.y : (__expf(v.y) - 1.f);
                    v.z = v.z > 0.f ? v.z : (__expf(v.z) - 1.f);
                    v.w = v.w > 0.f ? v.w : (__expf(v.w) - 1.f);
                }
                uint4 u = make_uint4(f2tf(v.x), f2tf(v.y), f2tf(v.z), f2tf(v.w));
                *(uint4*)(&S.As[r][kc + i * 4]) = u;
            }
        }
        {
            int k = tid >> 3, n0 = (tid & 7) * 8;
            #pragma unroll
            for (int i = 0; i < 2; i++) {
                float4 v = *(const float4*)(B + (long)(k0 + k) * D2 + n0 + i * 4);
                uint4 u = make_uint4(f2tf(v.x), f2tf(v.y), f2tf(v.z), f2tf(v.w));
                *(uint4*)(&S.Bs[k][n0 + i * 4]) = u;
            }
        }
        __syncthreads();
        gemm_tiles_mma(S, lane, wm, wn, acc);
    }
    gemm_store_c(C, D2, M, row0, lane, wm, wn, acc);
}

// ================= gather layer2 (writes final d_out) ========================
__global__ __launch_bounds__(256) void gather2_kernel(
    const int* __restrict__ rowptr, const int* __restrict__ srcs,
    const float* __restrict__ asrc, const float* __restrict__ adst,
    const float* __restrict__ xl, const float* __restrict__ b2,
    float* __restrict__ out) {
    int node = blockIdx.x * 8 + (threadIdx.x >> 5);
    if (node >= NNODES) return;
    int lane = threadIdx.x & 31;
    int beg = rowptr[node], end = rowptr[node + 1];
    float adv = adst[node];
    float acc0 = 0.f, acc1 = 0.f, exsum = 0.f;
    for (int base = beg; base < end; base += 32) {
        int j = base + lane;
        int sv = 0;
        float exv = 0.f;
        if (j < end) {
            sv = __ldg(srcs + j);
            float v = __ldg(asrc + sv) + adv;
            v = v > 0.f ? v : v * NEG_SLOPE;
            exv = __expf(v);
        }
        int m = min(32, end - base);
        for (int t = 0; t < m; t++) {
            int   s  = __shfl_sync(0xFFFFFFFFu, sv,  t);
            float ex = __shfl_sync(0xFFFFFFFFu, exv, t);
            exsum += ex;
            acc0 += ex * __ldg(xl + (long)s * D2 + lane);
            acc1 += ex * __ldg(xl + (long)s * D2 + lane + 32);
        }
    }
    float inv = 1.f / exsum;
    out[(long)node * D2 + lane]      = acc0 * inv + b2[lane];
    out[(long)node * D2 + lane + 32] = acc1 * inv + b2[lane + 32];
}

// ================= launch ====================================================
extern "C" void kernel_launch(void* const* d_in, const int* in_sizes, int n_in,
                              void* d_out, int out_size) {
    const float* x     = (const float*)d_in[0];
    const int*   ei    = (const int*)d_in[1];
    const float* W1    = (const float*)d_in[2];
    const float* at_s1 = (const float*)d_in[3];
    const float* at_d1 = (const float*)d_in[4];
    const float* b1    = (const float*)d_in[5];
    const float* W2    = (const float*)d_in[6];
    const float* at_s2 = (const float*)d_in[7];
    const float* at_d2 = (const float*)d_in[8];
    const float* b2    = (const float*)d_in[9];
    float* out = (float*)d_out;

    float *aggx, *agg1, *xl2, *ws1, *wd1, *as1, *ad1, *as2, *ad2;
    int *cnt, *rowptr, *wptr, *bsum, *boff, *srcs;
    cudaGetSymbolAddress((void**)&aggx,   g_aggx);
    cudaGetSymbolAddress((void**)&agg1,   g_agg1);
    cudaGetSymbolAddress((void**)&xl2,    g_xl2);
    cudaGetSymbolAddress((void**)&ws1,    g_ws1);
    cudaGetSymbolAddress((void**)&wd1,    g_wd1);
    cudaGetSymbolAddress((void**)&as1,    g_as1);
    cudaGetSymbolAddress((void**)&ad1,    g_ad1);
    cudaGetSymbolAddress((void**)&as2,    g_as2);
    cudaGetSymbolAddress((void**)&ad2,    g_ad2);
    cudaGetSymbolAddress((void**)&cnt,    g_cnt);
    cudaGetSymbolAddress((void**)&rowptr, g_rowptr);
    cudaGetSymbolAddress((void**)&wptr,   g_wptr);
    cudaGetSymbolAddress((void**)&bsum,   g_bsum);
    cudaGetSymbolAddress((void**)&boff,   g_boff);
    cudaGetSymbolAddress((void**)&srcs,   g_srcs);

    // ---- CSR build (by dst) ----
    zero_cnt<<<(NNODES + 255) / 256, 256>>>(cnt);
    hist_kernel<<<(ETOT + 255) / 256, 256>>>(ei, cnt);
    scan1_kernel<<<NBLK_SCAN, 256>>>(cnt, rowptr, bsum);
    scan2_kernel<<<1, 256>>>(bsum, boff);
    scan3_kernel<<<(NNODES + 255) / 256, 256>>>(rowptr, boff, wptr);
    scatter_kernel<<<(ETOT + 255) / 256, 256>>>(ei, wptr, srcs);

    // ---- layer 1 ----
    w1prep_kernel<<<1, 512>>>(W1, at_s1, at_d1, ws1, wd1);
    alpha1_kernel<<<(NNODES * 32 + 255) / 256, 256>>>(x, ws1, wd1, as1, ad1);
    gather1_kernel<<<(NNODES + 7) / 8, 256>>>(rowptr, srcs, as1, ad1, x, aggx);
    tf32_gemm_h<<<dim3(1, (NNODES + 127) / 128, H1), 256>>>(aggx, W1, agg1, NNODES);

    // ---- layer 2 ----
    tf32_gemm2<<<dim3(1, (NNODES + 127) / 128), 256>>>(agg1, b1, W2, xl2, NNODES);
    alpha2_kernel<<<(NNODES * 32 + 255) / 256, 256>>>(xl2, at_s2, at_d2, as2, ad2);
    gather2_kernel<<<(NNODES + 7) / 8, 256>>>(rowptr, srcs, as2, ad2, xl2, b2, out);
}